// round 15
// baseline (speedup 1.0000x reference)
#include <cuda_runtime.h>
#include <cuda_bf16.h>
#include <cuda_fp16.h>
#include <cstdint>

#define BATCHN 4096
#define SEQLEN 80
#define EMBD   100
#define UNITS  64
#define NG     256                 // 4*UNITS gates
#define PROWS  (79 * 128)          // vocab padded to m-tiles

// ---------------- device scratch (allocation-free: device globals) ----------
__device__ __nv_bfloat16 g_embbf[10000 * 128];           // emb->bf16, K padded to 128
__device__ __nv_bfloat16 g_Wt1  [256 * 128];             // W1^T bf16 [n][k], k padded
__device__ uint16_t      g_P    [(size_t)PROWS * 256];   // f16 table: emb@W1 + b1

// ---------------- helpers ---------------------------------------------------
__device__ __forceinline__ float tanhapx(float x) {
    float y; asm("tanh.approx.f32 %0, %1;" : "=f"(y) : "f"(x)); return y;
}
__device__ __forceinline__ uint32_t smem_u32(const void* p) {
    uint32_t a;
    asm("{ .reg .u64 t; cvta.to.shared.u64 t, %1; cvt.u32.u64 %0, t; }" : "=r"(a) : "l"(p));
    return a;
}
__device__ __forceinline__ uint32_t hmul2(uint32_t a, uint32_t b) {
    uint32_t d; asm("mul.rn.f16x2 %0,%1,%2;" : "=r"(d) : "r"(a), "r"(b)); return d;
}
__device__ __forceinline__ uint32_t hfma2(uint32_t a, uint32_t b, uint32_t c) {
    uint32_t d; asm("fma.rn.f16x2 %0,%1,%2,%3;" : "=r"(d) : "r"(a), "r"(b), "r"(c)); return d;
}
__device__ __forceinline__ uint32_t htanh2(uint32_t a) {
    uint32_t d; asm("tanh.approx.f16x2 %0,%1;" : "=r"(d) : "r"(a)); return d;
}
__device__ __forceinline__ uint32_t packh(float lo, float hi) {
    uint32_t d; asm("cvt.rn.f16x2.f32 %0,%1,%2;" : "=r"(d) : "f"(hi), "f"(lo)); return d;
}
__device__ __forceinline__ float2 h2tof2(uint32_t h) {
    float lo, hi;
    asm("{ .reg .b16 l,h; mov.b32 {l,h}, %2; cvt.f32.f16 %0, l; cvt.f32.f16 %1, h; }"
        : "=f"(lo), "=f"(hi) : "r"(h));
    return make_float2(lo, hi);
}
// bf16 HMMA, f32 acc (P-table GEMM only)
__device__ __forceinline__ void mma16816(float* d, const uint32_t* a, const uint32_t* b) {
    asm volatile(
        "mma.sync.aligned.m16n8k16.row.col.f32.bf16.bf16.f32 "
        "{%0,%1,%2,%3}, {%4,%5,%6,%7}, {%8,%9}, {%0,%1,%2,%3};"
        : "+f"(d[0]), "+f"(d[1]), "+f"(d[2]), "+f"(d[3])
        : "r"(a[0]), "r"(a[1]), "r"(a[2]), "r"(a[3]), "r"(b[0]), "r"(b[1]));
}
// f16 HMMA, f16 acc (scan)
__device__ __forceinline__ void mma16816hh(uint32_t* d, const uint32_t* a, const uint32_t* b) {
    asm volatile(
        "mma.sync.aligned.m16n8k16.row.col.f16.f16.f16.f16 "
        "{%0,%1}, {%2,%3,%4,%5}, {%6,%7}, {%0,%1};"
        : "+r"(d[0]), "+r"(d[1])
        : "r"(a[0]), "r"(a[1]), "r"(a[2]), "r"(a[3]), "r"(b[0]), "r"(b[1]));
}
__device__ __forceinline__ void ldmx4(uint32_t* r, uint32_t addr) {
    asm volatile("ldmatrix.sync.aligned.m8n8.x4.shared.b16 {%0,%1,%2,%3}, [%4];"
        : "=r"(r[0]), "=r"(r[1]), "=r"(r[2]), "=r"(r[3]) : "r"(addr));
}
__device__ __forceinline__ void cpa16(uint32_t dst, const void* gsrc) {
    asm volatile("{ .reg .u64 ga; cvta.to.global.u64 ga, %1; "
                 "cp.async.ca.shared.global [%0], [ga], 16; }"
                 :: "r"(dst), "l"(gsrc) : "memory");
}
#define CPA_COMMIT() asm volatile("cp.async.commit_group;" ::: "memory")
#define CPA_WAIT0()  asm volatile("cp.async.wait_group 0;" ::: "memory")
#define BAR512()     asm volatile("bar.sync 0, 512;" ::: "memory")

// f16x2 LSTM cell pair (R11 numerics)
__device__ __forceinline__ uint32_t lstm_cell2h(
    uint32_t zi, uint32_t zf, uint32_t zg, uint32_t zo, uint32_t& c2)
{
    const uint32_t H05 = 0x38003800u;   // (0.5, 0.5)
    uint32_t si = hfma2(htanh2(hmul2(zi, H05)), H05, H05);
    uint32_t sf = hfma2(htanh2(hmul2(zf, H05)), H05, H05);
    uint32_t tg = htanh2(zg);
    uint32_t so = hfma2(htanh2(hmul2(zo, H05)), H05, H05);
    c2 = hfma2(sf, c2, hmul2(si, tg));
    return hmul2(so, htanh2(c2));
}

// ---------------------------------------------------------------------------
// Pre-conversion kernels
// ---------------------------------------------------------------------------
__global__ void conv_emb_kernel(const float* __restrict__ emb) {
    int idx = blockIdx.x * 256 + threadIdx.x;
    int v = idx >> 7, c = idx & 127;
    g_embbf[idx] = (c < EMBD) ? __float2bfloat16(emb[v * EMBD + c]) : __nv_bfloat16(0.f);
}
__global__ void conv_w1_kernel(const float* __restrict__ W) {
    int idx = blockIdx.x * 256 + threadIdx.x;
    int n = idx >> 7, c = idx & 127;
    g_Wt1[idx] = (c < EMBD) ? __float2bfloat16(W[c * NG + n]) : __nv_bfloat16(0.f);
}

// ---------------------------------------------------------------------------
// P-table GEMM: P[v][0:256] = emb[v]@W1 + b1 (f16 out). Grid (2, 79).
// ---------------------------------------------------------------------------
__global__ void __launch_bounds__(256, 2) gemm_P(const float* __restrict__ bias)
{
    constexpr int K = 112, SA = K + 8, KH = K / 2;
    extern __shared__ __nv_bfloat16 smbf[];
    __nv_bfloat16* Asm = smbf;
    __nv_bfloat16* Bsm = smbf + 128 * SA;

    const int tid = threadIdx.x;
    const int m0  = blockIdx.y * 128;
    const int c0  = blockIdx.x * 128;

    for (int idx = tid; idx < 128 * KH; idx += 256) {
        int row = idx / KH, kc = (idx - row * KH) * 2;
        int m = m0 + row; if (m > 9999) m = 9999;
        *(uint32_t*)&Asm[row * SA + kc] = *(const uint32_t*)&g_embbf[(size_t)m * 128 + kc];
    }
    for (int idx = tid; idx < 128 * KH; idx += 256) {
        int row = idx / KH, kc = (idx - row * KH) * 2;
        *(uint32_t*)&Bsm[row * SA + kc] = *(const uint32_t*)&g_Wt1[(size_t)(c0 + row) * 128 + kc];
    }
    __syncthreads();

    const int wid  = tid >> 5, lid = tid & 31;
    const int wrow = wid & 3, wcol = wid >> 2;
    const int g    = lid >> 2, t = lid & 3;

    const uint32_t a_base = smem_u32(Asm);
    const uint32_t b_base = smem_u32(Bsm);
    const uint32_t a_lane = (uint32_t)((wrow * 32 + (lid & 15)) * SA * 2 + (lid >> 4) * 16);
    const uint32_t b_lane = (uint32_t)((wcol * 64 + (lid >> 4) * 8 + (lid & 7)) * SA * 2 +
                                       ((lid >> 3) & 1) * 16);

    float acc[2][8][4];
    #pragma unroll
    for (int mt = 0; mt < 2; mt++)
        #pragma unroll
        for (int nt = 0; nt < 8; nt++)
            #pragma unroll
            for (int r = 0; r < 4; r++) acc[mt][nt][r] = 0.f;

    #pragma unroll
    for (int s = 0; s < K / 16; s++) {
        uint32_t af[2][4], bfr[8][2];
        #pragma unroll
        for (int mt = 0; mt < 2; mt++)
            ldmx4(af[mt], a_base + a_lane + (uint32_t)(mt * 16 * SA * 2 + s * 32));
        #pragma unroll
        for (int np = 0; np < 4; np++) {
            uint32_t bq[4];
            ldmx4(bq, b_base + b_lane + (uint32_t)(np * 16 * SA * 2 + s * 32));
            bfr[np * 2][0] = bq[0]; bfr[np * 2][1] = bq[1];
            bfr[np * 2 + 1][0] = bq[2]; bfr[np * 2 + 1][1] = bq[3];
        }
        #pragma unroll
        for (int mt = 0; mt < 2; mt++)
            #pragma unroll
            for (int nt = 0; nt < 8; nt++)
                mma16816(acc[mt][nt], af[mt], bfr[nt]);
    }

    #pragma unroll
    for (int nt = 0; nt < 8; nt++) {
        const int col = c0 + wcol * 64 + nt * 8 + t * 2;
        float2 bb = *(const float2*)&bias[col];
        #pragma unroll
        for (int mt = 0; mt < 2; mt++) {
            const int row = m0 + wrow * 32 + mt * 16 + g;
            *(uint32_t*)&g_P[(size_t)row * 256 + col] =
                packh(acc[mt][nt][0] + bb.x, acc[mt][nt][1] + bb.y);
            *(uint32_t*)&g_P[(size_t)(row + 8) * 256 + col] =
                packh(acc[mt][nt][2] + bb.x, acc[mt][nt][3] + bb.y);
        }
    }
}

// ---------------------------------------------------------------------------
// Lag-2 balanced warp-specialized scan: 128 CTAs x 512 thr, 32 rows/CTA.
// Iter t (0..81), ONE bar.sync 0,512 per iter:
//  L1 (warps 0-7), t=0..79: h1(t) = cell(P[tok] + h1(t-1)@U1);
//     t=0..80: z2p(t) = b2[i,f] + h1(t-1)@W2[g0,g1] (SHARES h1 A-fragments)
//     -> z2p double buffer. 48 mma/warp.
//  L2 (warps 8-15), t=2..81: h2(t-2) = cell(z2p + h1(t-2)@W2[g2,g3]
//     + h2(t-3)@U2). 48 mma/warp.
//  h1 = 3-slot ring (slots t, t-1, t-2 distinct mod 3); h2, z2p double-buffered.
// ---------------------------------------------------------------------------
#define XS_OFF   0                     // 2 x 32 x 528  = 33792 (f16 P rows)
#define H1_OFF   33792                 // 3 x 32 x 144  = 13824 (ring)
#define H2_OFF   47616                 // 2 x 32 x 144  = 9216
#define Z2P_OFF  56832                 // 2 x 2 x 32 x 144 = 18432
#define TOK_OFF  75264                 // 32 x 80 x 2   = 5120
#define SM_TOTAL 80384

__global__ void __launch_bounds__(512, 1) lstm_ws(
    const int*   __restrict__ tokens,
    const float* __restrict__ U1,
    const float* __restrict__ W2,
    const float* __restrict__ U2,
    const float* __restrict__ b2,
    const float* __restrict__ Wd,
    const float* __restrict__ bd,
    float*       __restrict__ out)
{
    extern __shared__ char sm[];
    const int tid = threadIdx.x, wid = tid >> 5, lid = tid & 31;
    const int g = lid >> 2, t4 = lid & 3;
    const int w8 = wid & 7;
    const int b0 = blockIdx.x * 32;

    uint16_t* toks = (uint16_t*)(sm + TOK_OFF);

    {   // zero h1 ring + h2 buffers (z2p needs no zeroing)
        uint32_t* z1 = (uint32_t*)(sm + H1_OFF);
        for (int i = tid; i < (13824 + 9216) / 4; i += 512) z1[i] = 0u;
    }
    for (int idx = tid; idx < 32 * SEQLEN; idx += 512)
        toks[idx] = (uint16_t)tokens[(size_t)(b0 + idx / SEQLEN) * SEQLEN + idx % SEQLEN];
    __syncthreads();

    const uint32_t xs_b = smem_u32(sm + XS_OFF);
    const uint32_t h1b  = smem_u32(sm + H1_OFF);          // slot s: +s*4608
    const uint32_t h2b0 = smem_u32(sm + H2_OFF), h2b1 = h2b0 + 4608;
    const uint32_t a_lane_h = (uint32_t)((lid & 15) * 144 + (lid >> 4) * 16);
    const int colb = (w8 * 8 + t4 * 2) * 2;

    if (wid < 8) {
        // =================== L1 group (layer 1 + z2p precompute) ===========
        auto stage_x = [&](int buf, int t) {
            const uint32_t dbase = xs_b + buf * 16896;
            #pragma unroll
            for (int i = 0; i < 4; i++) {
                int idx = tid + i * 256;
                int row = idx >> 5, ch = idx & 31;
                cpa16(dbase + row * 528 + ch * 16,
                      g_P + (size_t)toks[row * SEQLEN + t] * 256 + ch * 8);
            }
        };
        stage_x(0, 0);
        CPA_COMMIT();

        uint32_t bu1[4][4][2], bw2p[2][4][2], rb2p[2];
        #pragma unroll
        for (int gg = 0; gg < 4; gg++) {
            const int n = gg * 64 + w8 * 8 + g;
            #pragma unroll
            for (int kt = 0; kt < 4; kt++) {
                const int k0 = kt * 16 + t4 * 2;
                bu1[gg][kt][0] = packh(U1[(size_t)k0 * NG + n],       U1[(size_t)(k0 + 1) * NG + n]);
                bu1[gg][kt][1] = packh(U1[(size_t)(k0 + 8) * NG + n], U1[(size_t)(k0 + 9) * NG + n]);
                if (gg < 2) {
                    bw2p[gg][kt][0] = packh(W2[(size_t)k0 * NG + n],       W2[(size_t)(k0 + 1) * NG + n]);
                    bw2p[gg][kt][1] = packh(W2[(size_t)(k0 + 8) * NG + n], W2[(size_t)(k0 + 9) * NG + n]);
                }
            }
            if (gg < 2) {
                const int col = gg * 64 + w8 * 8 + t4 * 2;
                rb2p[gg] = packh(b2[col], b2[col + 1]);
            }
        }
        CPA_WAIT0();
        asm volatile("bar.sync 7, 256;" ::: "memory");    // xs(0) visible in L1

        uint32_t c1[2][2] = {{0u, 0u}, {0u, 0u}};

        // ---- iter 0: h1(0) = cell(x(0)) -> slot 0; z2p(0) = rb2p ----
        stage_x(1, 1);
        CPA_COMMIT();
        {
            const char* xb = sm + XS_OFF;
            char* h1wr = sm + H1_OFF;                     // slot 0
            #pragma unroll
            for (int mt = 0; mt < 2; mt++)
                #pragma unroll
                for (int rs = 0; rs < 2; rs++) {
                    const int row = mt * 16 + g + rs * 8;
                    uint32_t z0 = *(const uint32_t*)(xb + row * 528 + 0 * 128 + colb);
                    uint32_t z1v = *(const uint32_t*)(xb + row * 528 + 1 * 128 + colb);
                    uint32_t z2 = *(const uint32_t*)(xb + row * 528 + 2 * 128 + colb);
                    uint32_t z3 = *(const uint32_t*)(xb + row * 528 + 3 * 128 + colb);
                    uint32_t hv = lstm_cell2h(z0, z1v, z2, z3, c1[mt][rs]);
                    *(uint32_t*)(h1wr + row * 144 + colb) = hv;
                }
            char* zp = sm + Z2P_OFF;                      // buf 0
            #pragma unroll
            for (int gg = 0; gg < 2; gg++)
                #pragma unroll
                for (int mt = 0; mt < 2; mt++)
                    #pragma unroll
                    for (int rs = 0; rs < 2; rs++) {
                        const int row = mt * 16 + g + rs * 8;
                        *(uint32_t*)(zp + gg * 4608 + row * 144 + colb) = rb2p[gg];
                    }
        }
        CPA_WAIT0();
        BAR512();                                         // iter 0

        // ---- iters 1..79: full body ----
        for (int t = 1; t < SEQLEN; ++t) {
            if (t + 1 < SEQLEN) stage_x((t + 1) & 1, t + 1);
            CPA_COMMIT();

            const uint32_t h1rd = h1b + (uint32_t)(((t - 1) % 3) * 4608);
            uint32_t acc1[2][4][2], accp[2][2][2];
            const char* xb = sm + XS_OFF + (t & 1) * 16896;
            #pragma unroll
            for (int mt = 0; mt < 2; mt++) {
                #pragma unroll
                for (int gg = 0; gg < 4; gg++) {
                    acc1[mt][gg][0] = *(const uint32_t*)(xb + (mt * 16 + g) * 528 + gg * 128 + colb);
                    acc1[mt][gg][1] = *(const uint32_t*)(xb + (mt * 16 + g + 8) * 528 + gg * 128 + colb);
                }
                #pragma unroll
                for (int gg = 0; gg < 2; gg++) { accp[mt][gg][0] = rb2p[gg]; accp[mt][gg][1] = rb2p[gg]; }
            }
            #pragma unroll
            for (int kt = 0; kt < 4; kt++) {
                uint32_t a0[4], a1[4];
                ldmx4(a0, h1rd + a_lane_h + (uint32_t)(kt * 32));
                ldmx4(a1, h1rd + a_lane_h + (uint32_t)(16 * 144 + kt * 32));
                #pragma unroll
                for (int gg = 0; gg < 4; gg++) {
                    mma16816hh(acc1[0][gg], a0, bu1[gg][kt]);
                    mma16816hh(acc1[1][gg], a1, bu1[gg][kt]);
                }
                #pragma unroll
                for (int gg = 0; gg < 2; gg++) {
                    mma16816hh(accp[0][gg], a0, bw2p[gg][kt]);
                    mma16816hh(accp[1][gg], a1, bw2p[gg][kt]);
                }
            }
            char* h1wr = sm + H1_OFF + (t % 3) * 4608;
            char* zp   = sm + Z2P_OFF + (t & 1) * 9216;
            #pragma unroll
            for (int mt = 0; mt < 2; mt++)
                #pragma unroll
                for (int rs = 0; rs < 2; rs++) {
                    const int row = mt * 16 + g + rs * 8;
                    uint32_t hv = lstm_cell2h(acc1[mt][0][rs], acc1[mt][1][rs],
                                              acc1[mt][2][rs], acc1[mt][3][rs], c1[mt][rs]);
                    *(uint32_t*)(h1wr + row * 144 + colb) = hv;
                    *(uint32_t*)(zp + 0 * 4608 + row * 144 + colb) = accp[mt][0][rs];
                    *(uint32_t*)(zp + 1 * 4608 + row * 144 + colb) = accp[mt][1][rs];
                }
            CPA_WAIT0();
            BAR512();                                     // iters 1..79
        }

        // ---- iter 80: z2p(80) only (h1(79) frags, slot (80-1)%3 = 1) ----
        {
            const uint32_t h1rd = h1b + (uint32_t)(((SEQLEN - 1) % 3) * 4608);
            uint32_t accp[2][2][2];
            #pragma unroll
            for (int mt = 0; mt < 2; mt++)
                #pragma unroll
                for (int gg = 0; gg < 2; gg++) { accp[mt][gg][0] = rb2p[gg]; accp[mt][gg][1] = rb2p[gg]; }
            #pragma unroll
            for (int kt = 0; kt < 4; kt++) {
                uint32_t a0[4], a1[4];
                ldmx4(a0, h1rd + a_lane_h + (uint32_t)(kt * 32));
                ldmx4(a1, h1rd + a_lane_h + (uint32_t)(16 * 144 + kt * 32));
                #pragma unroll
                for (int gg = 0; gg < 2; gg++) {
                    mma16816hh(accp[0][gg], a0, bw2p[gg][kt]);
                    mma16816hh(accp[1][gg], a1, bw2p[gg][kt]);
                }
            }
            char* zp = sm + Z2P_OFF + (SEQLEN & 1) * 9216;   // buf (80&1)=0
            #pragma unroll
            for (int mt = 0; mt < 2; mt++)
                #pragma unroll
                for (int rs = 0; rs < 2; rs++) {
                    const int row = mt * 16 + g + rs * 8;
                    *(uint32_t*)(zp + 0 * 4608 + row * 144 + colb) = accp[mt][0][rs];
                    *(uint32_t*)(zp + 1 * 4608 + row * 144 + colb) = accp[mt][1][rs];
                }
        }
        BAR512();                                         // iter 80
        BAR512();                                         // iter 81
    } else {
        // =================== L2 group (layer 2, lag 2) =====================
        uint32_t bw2g[2][4][2], bu2[4][4][2], rb2g[2];
        #pragma unroll
        for (int gg = 0; gg < 4; gg++) {
            const int n = gg * 64 + w8 * 8 + g;
            #pragma unroll
            for (int kt = 0; kt < 4; kt++) {
                const int k0 = kt * 16 + t4 * 2;
                bu2[gg][kt][0] = packh(U2[(size_t)k0 * NG + n],       U2[(size_t)(k0 + 1) * NG + n]);
                bu2[gg][kt][1] = packh(U2[(size_t)(k0 + 8) * NG + n], U2[(size_t)(k0 + 9) * NG + n]);
                if (gg >= 2) {
                    bw2g[gg - 2][kt][0] = packh(W2[(size_t)k0 * NG + n],       W2[(size_t)(k0 + 1) * NG + n]);
                    bw2g[gg - 2][kt][1] = packh(W2[(size_t)(k0 + 8) * NG + n], W2[(size_t)(k0 + 9) * NG + n]);
                }
            }
            if (gg >= 2) {
                const int col = gg * 64 + w8 * 8 + t4 * 2;
                rb2g[gg - 2] = packh(b2[col], b2[col + 1]);
            }
        }
        BAR512();                                         // iter 0
        BAR512();                                         // iter 1

        uint32_t c2s[2][2] = {{0u, 0u}, {0u, 0u}};

        for (int t = 2; t <= SEQLEN + 1; ++t) {
            // h2(t-2) = cell(z2p(t-1) [gates 0,1] + h1(t-2)@W2[2,3] + h2(t-3)@U2)
            const uint32_t h1rd = h1b + (uint32_t)(((t - 2) % 3) * 4608);
            const uint32_t h2rd = (t & 1) ? h2b0 : h2b1;  // buf ((t&1)^1)
            const char* zp = sm + Z2P_OFF + ((t - 1) & 1) * 9216;

            uint32_t acc2[2][4][2];
            #pragma unroll
            for (int mt = 0; mt < 2; mt++) {
                #pragma unroll
                for (int rs = 0; rs < 2; rs++) {
                    const int row = mt * 16 + g + rs * 8;
                    acc2[mt][0][rs] = *(const uint32_t*)(zp + 0 * 4608 + row * 144 + colb);
                    acc2[mt][1][rs] = *(const uint32_t*)(zp + 1 * 4608 + row * 144 + colb);
                }
                acc2[mt][2][0] = rb2g[0]; acc2[mt][2][1] = rb2g[0];
                acc2[mt][3][0] = rb2g[1]; acc2[mt][3][1] = rb2g[1];
            }
            #pragma unroll
            for (int kt = 0; kt < 4; kt++) {
                uint32_t a0[4], a1[4];
                ldmx4(a0, h1rd + a_lane_h + (uint32_t)(kt * 32));
                ldmx4(a1, h1rd + a_lane_h + (uint32_t)(16 * 144 + kt * 32));
                #pragma unroll
                for (int gg = 0; gg < 2; gg++) {
                    mma16816hh(acc2[0][gg + 2], a0, bw2g[gg][kt]);
                    mma16816hh(acc2[1][gg + 2], a1, bw2g[gg][kt]);
                }
            }
            #pragma unroll
            for (int kt = 0; kt < 4; kt++) {
                uint32_t a0[4], a1[4];
                ldmx4(a0, h2rd + a_lane_h + (uint32_t)(kt * 32));
                ldmx4(a1, h2rd + a_lane_h + (uint32_t)(16 * 144 + kt * 32));
                #pragma unroll
                for (int gg = 0; gg < 4; gg++) {
                    mma16816hh(acc2[0][gg], a0, bu2[gg][kt]);
                    mma16816hh(acc2[1][gg], a1, bu2[gg][kt]);
                }
            }
            if (t <= SEQLEN) {
                char* h2wr = sm + H2_OFF + (t & 1) * 4608;
                #pragma unroll
                for (int mt = 0; mt < 2; mt++)
                    #pragma unroll
                    for (int rs = 0; rs < 2; rs++) {
                        const int row = mt * 16 + g + rs * 8;
                        uint32_t hv = lstm_cell2h(acc2[mt][0][rs], acc2[mt][1][rs],
                                                  acc2[mt][2][rs], acc2[mt][3][rs], c2s[mt][rs]);
                        *(uint32_t*)(h2wr + row * 144 + colb) = hv;
                    }
            } else {
                float (*hfin)[68] = reinterpret_cast<float(*)[68]>(sm + XS_OFF);
                #pragma unroll
                for (int mt = 0; mt < 2; mt++)
                    #pragma unroll
                    for (int rs = 0; rs < 2; rs++) {
                        const int row = mt * 16 + g + rs * 8;
                        uint32_t hv = lstm_cell2h(acc2[mt][0][rs], acc2[mt][1][rs],
                                                  acc2[mt][2][rs], acc2[mt][3][rs], c2s[mt][rs]);
                        float2 f = h2tof2(hv);
                        hfin[row][w8 * 8 + t4 * 2]     = f.x;
                        hfin[row][w8 * 8 + t4 * 2 + 1] = f.y;
                    }
            }
            BAR512();                                     // iters 2..81
        }
    }

    // -------------------- dense head --------------------
    if (tid < 32) {
        float (*hfin)[68] = reinterpret_cast<float(*)[68]>(sm + XS_OFF);
        float s = bd[0];
        #pragma unroll
        for (int u = 0; u < 64; u++) s += hfin[tid][u] * Wd[u];
        out[b0 + tid] = fmaf(0.5f, tanhapx(0.5f * s), 0.5f);
    }
}

// ---------------------------------------------------------------------------
extern "C" void kernel_launch(void* const* d_in, const int* in_sizes, int n_in,
                              void* d_out, int out_size)
{
    const int*   tokens = (const int*)  d_in[0];
    const float* emb    = (const float*)d_in[1];
    const float* W1     = (const float*)d_in[2];
    const float* U1     = (const float*)d_in[3];
    const float* b1     = (const float*)d_in[4];
    const float* W2     = (const float*)d_in[5];
    const float* U2     = (const float*)d_in[6];
    const float* b2     = (const float*)d_in[7];
    const float* Wd     = (const float*)d_in[8];
    const float* bd     = (const float*)d_in[9];
    float* out = (float*)d_out;

    const int smem_gp = 2 * 128 * (112 + 8) * 2;   // 61440
    cudaFuncSetAttribute(gemm_P,  cudaFuncAttributeMaxDynamicSharedMemorySize, smem_gp);
    cudaFuncSetAttribute(lstm_ws, cudaFuncAttributeMaxDynamicSharedMemorySize, SM_TOTAL);

    conv_emb_kernel<<<10000 * 128 / 256, 256>>>(emb);
    conv_w1_kernel<<<256 * 128 / 256, 256>>>(W1);
    dim3 pgrid(2, 79);
    gemm_P<<<pgrid, 256, smem_gp>>>(b1);

    lstm_ws<<<BATCHN / 32, 512, SM_TOTAL>>>(tokens, U1, W2, U2, b2, Wd, bd, out);
}

// round 16
// speedup vs baseline: 1.1370x; 1.1370x over previous
#include <cuda_runtime.h>
#include <cuda_bf16.h>
#include <cuda_fp16.h>
#include <cstdint>

#define BATCHN 4096
#define SEQLEN 80
#define EMBD   100
#define UNITS  64
#define NG     256                 // 4*UNITS gates
#define PROWS  (79 * 128)          // vocab padded to m-tiles

// ---------------- device scratch (allocation-free: device globals) ----------
__device__ __nv_bfloat16 g_Wt1[256 * 128];               // W1^T bf16 [n][k], k padded
__device__ uint16_t      g_P  [(size_t)PROWS * 256];     // f16 table: emb@W1 + b1

// ---------------- helpers ---------------------------------------------------
__device__ __forceinline__ float tanhapx(float x) {
    float y; asm("tanh.approx.f32 %0, %1;" : "=f"(y) : "f"(x)); return y;
}
__device__ __forceinline__ uint32_t smem_u32(const void* p) {
    uint32_t a;
    asm("{ .reg .u64 t; cvta.to.shared.u64 t, %1; cvt.u32.u64 %0, t; }" : "=r"(a) : "l"(p));
    return a;
}
__device__ __forceinline__ uint32_t hmul2(uint32_t a, uint32_t b) {
    uint32_t d; asm("mul.rn.f16x2 %0,%1,%2;" : "=r"(d) : "r"(a), "r"(b)); return d;
}
__device__ __forceinline__ uint32_t hfma2(uint32_t a, uint32_t b, uint32_t c) {
    uint32_t d; asm("fma.rn.f16x2 %0,%1,%2,%3;" : "=r"(d) : "r"(a), "r"(b), "r"(c)); return d;
}
__device__ __forceinline__ uint32_t htanh2(uint32_t a) {
    uint32_t d; asm("tanh.approx.f16x2 %0,%1;" : "=r"(d) : "r"(a)); return d;
}
__device__ __forceinline__ uint32_t packh(float lo, float hi) {
    uint32_t d; asm("cvt.rn.f16x2.f32 %0,%1,%2;" : "=r"(d) : "f"(hi), "f"(lo)); return d;
}
__device__ __forceinline__ float2 h2tof2(uint32_t h) {
    float lo, hi;
    asm("{ .reg .b16 l,h; mov.b32 {l,h}, %2; cvt.f32.f16 %0, l; cvt.f32.f16 %1, h; }"
        : "=f"(lo), "=f"(hi) : "r"(h));
    return make_float2(lo, hi);
}
// bf16 HMMA, f32 acc (P-table GEMM only)
__device__ __forceinline__ void mma16816(float* d, const uint32_t* a, const uint32_t* b) {
    asm volatile(
        "mma.sync.aligned.m16n8k16.row.col.f32.bf16.bf16.f32 "
        "{%0,%1,%2,%3}, {%4,%5,%6,%7}, {%8,%9}, {%0,%1,%2,%3};"
        : "+f"(d[0]), "+f"(d[1]), "+f"(d[2]), "+f"(d[3])
        : "r"(a[0]), "r"(a[1]), "r"(a[2]), "r"(a[3]), "r"(b[0]), "r"(b[1]));
}
// f16 HMMA, f16 acc (scan)
__device__ __forceinline__ void mma16816hh(uint32_t* d, const uint32_t* a, const uint32_t* b) {
    asm volatile(
        "mma.sync.aligned.m16n8k16.row.col.f16.f16.f16.f16 "
        "{%0,%1}, {%2,%3,%4,%5}, {%6,%7}, {%0,%1};"
        : "+r"(d[0]), "+r"(d[1])
        : "r"(a[0]), "r"(a[1]), "r"(a[2]), "r"(a[3]), "r"(b[0]), "r"(b[1]));
}
__device__ __forceinline__ void ldmx4(uint32_t* r, uint32_t addr) {
    asm volatile("ldmatrix.sync.aligned.m8n8.x4.shared.b16 {%0,%1,%2,%3}, [%4];"
        : "=r"(r[0]), "=r"(r[1]), "=r"(r[2]), "=r"(r[3]) : "r"(addr));
}
__device__ __forceinline__ void cpa16(uint32_t dst, const void* gsrc) {
    asm volatile("{ .reg .u64 ga; cvta.to.global.u64 ga, %1; "
                 "cp.async.cg.shared.global [%0], [ga], 16; }"
                 :: "r"(dst), "l"(gsrc) : "memory");
}
#define CPA_COMMIT() asm volatile("cp.async.commit_group;" ::: "memory")
#define CPA_WAIT0()  asm volatile("cp.async.wait_group 0;" ::: "memory")
#define BAR512()     asm volatile("bar.sync 0, 512;" ::: "memory")

// f16x2 LSTM cell pair (R11 numerics: sigmoid via 0.5*tanh(0.5x)+0.5)
__device__ __forceinline__ uint32_t lstm_cell2h(
    uint32_t zi, uint32_t zf, uint32_t zg, uint32_t zo, uint32_t& c2)
{
    const uint32_t H05 = 0x38003800u;   // (0.5, 0.5)
    uint32_t si = hfma2(htanh2(hmul2(zi, H05)), H05, H05);
    uint32_t sf = hfma2(htanh2(hmul2(zf, H05)), H05, H05);
    uint32_t tg = htanh2(zg);
    uint32_t so = hfma2(htanh2(hmul2(zo, H05)), H05, H05);
    c2 = hfma2(sf, c2, hmul2(si, tg));
    return hmul2(so, htanh2(c2));
}

// ---------------------------------------------------------------------------
// W1 transpose + bf16 conversion (tiny, 128 blocks)
// ---------------------------------------------------------------------------
__global__ void conv_w1_kernel(const float* __restrict__ W) {
    int idx = blockIdx.x * 256 + threadIdx.x;            // over 256*128
    int n = idx >> 7, c = idx & 127;
    g_Wt1[idx] = (c < EMBD) ? __float2bfloat16(W[c * NG + n]) : __nv_bfloat16(0.f);
}

// ---------------------------------------------------------------------------
// P-table GEMM: P[v][0:256] = emb[v]@W1 + b1 (f16 out). Grid (2, 79).
// emb f32 -> bf16 conversion fused into A staging (conv_emb kernel deleted).
// ---------------------------------------------------------------------------
__global__ void __launch_bounds__(256, 2) gemm_P(
    const float* __restrict__ emb, const float* __restrict__ bias)
{
    constexpr int K = 112, SA = K + 8, KH = K / 2;
    extern __shared__ __nv_bfloat16 smbf[];
    __nv_bfloat16* Asm = smbf;
    __nv_bfloat16* Bsm = smbf + 128 * SA;

    const int tid = threadIdx.x;
    const int m0  = blockIdx.y * 128;
    const int c0  = blockIdx.x * 128;

    // stage A: gather emb rows, convert f32->bf16 inline, zero-pad K to 112
    for (int idx = tid; idx < 128 * KH; idx += 256) {
        int row = idx / KH, kc = (idx - row * KH) * 2;
        int m = m0 + row; if (m > 9999) m = 9999;
        float f0 = 0.f, f1 = 0.f;
        if (kc < EMBD) {                 // kc even, EMBD=100 -> kc+1 < EMBD too
            const float* e = emb + (size_t)m * EMBD + kc;
            f0 = e[0]; f1 = e[1];
        }
        __nv_bfloat162 v = __float22bfloat162_rn(make_float2(f0, f1));
        *(uint32_t*)&Asm[row * SA + kc] = *(uint32_t*)&v;
    }
    for (int idx = tid; idx < 128 * KH; idx += 256) {
        int row = idx / KH, kc = (idx - row * KH) * 2;
        *(uint32_t*)&Bsm[row * SA + kc] = *(const uint32_t*)&g_Wt1[(size_t)(c0 + row) * 128 + kc];
    }
    __syncthreads();

    const int wid  = tid >> 5, lid = tid & 31;
    const int wrow = wid & 3, wcol = wid >> 2;
    const int g    = lid >> 2, t = lid & 3;

    const uint32_t a_base = smem_u32(Asm);
    const uint32_t b_base = smem_u32(Bsm);
    const uint32_t a_lane = (uint32_t)((wrow * 32 + (lid & 15)) * SA * 2 + (lid >> 4) * 16);
    const uint32_t b_lane = (uint32_t)((wcol * 64 + (lid >> 4) * 8 + (lid & 7)) * SA * 2 +
                                       ((lid >> 3) & 1) * 16);

    float acc[2][8][4];
    #pragma unroll
    for (int mt = 0; mt < 2; mt++)
        #pragma unroll
        for (int nt = 0; nt < 8; nt++)
            #pragma unroll
            for (int r = 0; r < 4; r++) acc[mt][nt][r] = 0.f;

    #pragma unroll
    for (int s = 0; s < K / 16; s++) {
        uint32_t af[2][4], bfr[8][2];
        #pragma unroll
        for (int mt = 0; mt < 2; mt++)
            ldmx4(af[mt], a_base + a_lane + (uint32_t)(mt * 16 * SA * 2 + s * 32));
        #pragma unroll
        for (int np = 0; np < 4; np++) {
            uint32_t bq[4];
            ldmx4(bq, b_base + b_lane + (uint32_t)(np * 16 * SA * 2 + s * 32));
            bfr[np * 2][0] = bq[0]; bfr[np * 2][1] = bq[1];
            bfr[np * 2 + 1][0] = bq[2]; bfr[np * 2 + 1][1] = bq[3];
        }
        #pragma unroll
        for (int mt = 0; mt < 2; mt++)
            #pragma unroll
            for (int nt = 0; nt < 8; nt++)
                mma16816(acc[mt][nt], af[mt], bfr[nt]);
    }

    #pragma unroll
    for (int nt = 0; nt < 8; nt++) {
        const int col = c0 + wcol * 64 + nt * 8 + t * 2;
        float2 bb = *(const float2*)&bias[col];
        #pragma unroll
        for (int mt = 0; mt < 2; mt++) {
            const int row = m0 + wrow * 32 + mt * 16 + g;
            *(uint32_t*)&g_P[(size_t)row * 256 + col] =
                packh(acc[mt][nt][0] + bb.x, acc[mt][nt][1] + bb.y);
            *(uint32_t*)&g_P[(size_t)(row + 8) * 256 + col] =
                packh(acc[mt][nt][2] + bb.x, acc[mt][nt][3] + bb.y);
        }
    }
}

// ---------------------------------------------------------------------------
// Warp-specialized fused scan (exact R11 best: 129.8us): 128 CTAs x 512 thr.
// Warps 0-7  (L1): z1 = P[token] + h1@U1
// Warps 8-15 (L2): z2 = b2 + h1@W2 + h2@U2, lag 1
// One bar.sync 0,512 per step.
// ---------------------------------------------------------------------------
#define XS_OFF  0                      // 2 x 32 x 528  = 33792 (f16 P rows)
#define H1_OFF  33792                  // 2 x 32 x 144  = 9216
#define H2_OFF  43008                  // 9216
#define TOK_OFF 52224                  // 32 x 80 x 2   = 5120
#define SM_TOTAL 57344

__global__ void __launch_bounds__(512, 1) lstm_ws(
    const int*   __restrict__ tokens,
    const float* __restrict__ U1,
    const float* __restrict__ W2,
    const float* __restrict__ U2,
    const float* __restrict__ b2,
    const float* __restrict__ Wd,
    const float* __restrict__ bd,
    float*       __restrict__ out)
{
    extern __shared__ char sm[];
    const int tid = threadIdx.x, wid = tid >> 5, lid = tid & 31;
    const int g = lid >> 2, t4 = lid & 3;
    const int w8 = wid & 7;
    const int b0 = blockIdx.x * 32;

    uint16_t* toks = (uint16_t*)(sm + TOK_OFF);

    {   // zero h buffers (exactly h1+h2: 18432 bytes)
        uint32_t* z1 = (uint32_t*)(sm + H1_OFF);
        for (int i = tid; i < 18432 / 4; i += 512) z1[i] = 0u;
    }
    for (int idx = tid; idx < 32 * SEQLEN; idx += 512)
        toks[idx] = (uint16_t)tokens[(size_t)(b0 + idx / SEQLEN) * SEQLEN + idx % SEQLEN];
    __syncthreads();

    const uint32_t xs_b = smem_u32(sm + XS_OFF);
    const uint32_t h1b0 = smem_u32(sm + H1_OFF), h1b1 = h1b0 + 4608;
    const uint32_t h2b0 = smem_u32(sm + H2_OFF), h2b1 = h2b0 + 4608;
    const uint32_t a_lane_h = (uint32_t)((lid & 15) * 144 + (lid >> 4) * 16);
    const int colb = (w8 * 8 + t4 * 2) * 2;

    if (wid < 8) {
        // =================== layer-1 group ===================
        auto stage_x = [&](int buf, int t) {
            const uint32_t dbase = xs_b + buf * 16896;
            #pragma unroll
            for (int i = 0; i < 4; i++) {
                int idx = tid + i * 256;       // 32 rows x 32 chunks of 16B
                int row = idx >> 5, ch = idx & 31;
                cpa16(dbase + row * 528 + ch * 16,
                      g_P + (size_t)toks[row * SEQLEN + t] * 256 + ch * 8);
            }
        };
        stage_x(0, 0);
        CPA_COMMIT();

        uint32_t bu1[4][4][2];
        #pragma unroll
        for (int gg = 0; gg < 4; gg++) {
            const int n = gg * 64 + w8 * 8 + g;
            #pragma unroll
            for (int kt = 0; kt < 4; kt++) {
                const int k0 = kt * 16 + t4 * 2;
                bu1[gg][kt][0] = packh(U1[(size_t)k0 * NG + n],       U1[(size_t)(k0 + 1) * NG + n]);
                bu1[gg][kt][1] = packh(U1[(size_t)(k0 + 8) * NG + n], U1[(size_t)(k0 + 9) * NG + n]);
            }
        }
        CPA_WAIT0();
        BAR512();                                   // bar0: x(0)+weights ready

        uint32_t c1[2][2] = {{0u, 0u}, {0u, 0u}};

        // ---- t = 0 peel: h1(0) = cell(x(0)); stage x(1) ----
        stage_x(1, 1);
        CPA_COMMIT();
        {
            const char* xb = sm + XS_OFF;
            char* h1wr = sm + H1_OFF + 4608;        // buf1
            #pragma unroll
            for (int mt = 0; mt < 2; mt++)
                #pragma unroll
                for (int rs = 0; rs < 2; rs++) {
                    const int row = mt * 16 + g + rs * 8;
                    uint32_t z0 = *(const uint32_t*)(xb + row * 528 + 0 * 128 + colb);
                    uint32_t z1v = *(const uint32_t*)(xb + row * 528 + 1 * 128 + colb);
                    uint32_t z2 = *(const uint32_t*)(xb + row * 528 + 2 * 128 + colb);
                    uint32_t z3 = *(const uint32_t*)(xb + row * 528 + 3 * 128 + colb);
                    uint32_t hv = lstm_cell2h(z0, z1v, z2, z3, c1[mt][rs]);
                    *(uint32_t*)(h1wr + row * 144 + colb) = hv;
                }
        }
        CPA_WAIT0();
        BAR512();                                   // bar1

        for (int t = 1; t < SEQLEN; ++t) {
            if (t + 1 < SEQLEN) stage_x((t + 1) & 1, t + 1);
            CPA_COMMIT();

            const uint32_t h1rd = (t & 1) ? h1b1 : h1b0;
            uint32_t acc1[2][4][2];
            const char* xb = sm + XS_OFF + (t & 1) * 16896;
            #pragma unroll
            for (int mt = 0; mt < 2; mt++)
                #pragma unroll
                for (int gg = 0; gg < 4; gg++) {
                    acc1[mt][gg][0] = *(const uint32_t*)(xb + (mt * 16 + g) * 528 + gg * 128 + colb);
                    acc1[mt][gg][1] = *(const uint32_t*)(xb + (mt * 16 + g + 8) * 528 + gg * 128 + colb);
                }
            #pragma unroll
            for (int kt = 0; kt < 4; kt++) {
                uint32_t a0[4], a1[4];
                ldmx4(a0, h1rd + a_lane_h + (uint32_t)(kt * 32));
                ldmx4(a1, h1rd + a_lane_h + (uint32_t)(16 * 144 + kt * 32));
                #pragma unroll
                for (int gg = 0; gg < 4; gg++) {
                    mma16816hh(acc1[0][gg], a0, bu1[gg][kt]);
                    mma16816hh(acc1[1][gg], a1, bu1[gg][kt]);
                }
            }
            char* h1wr = sm + H1_OFF + ((t & 1) ^ 1) * 4608;
            #pragma unroll
            for (int mt = 0; mt < 2; mt++)
                #pragma unroll
                for (int rs = 0; rs < 2; rs++) {
                    const int row = mt * 16 + g + rs * 8;
                    uint32_t hv = lstm_cell2h(acc1[mt][0][rs], acc1[mt][1][rs],
                                              acc1[mt][2][rs], acc1[mt][3][rs], c1[mt][rs]);
                    *(uint32_t*)(h1wr + row * 144 + colb) = hv;
                }
            CPA_WAIT0();
            BAR512();                               // bar2..80
        }
        BAR512();                                   // bar81 (final)
    } else {
        // =================== layer-2 group ===================
        uint32_t bw2[4][4][2], bu2[4][4][2], rb2[4];
        #pragma unroll
        for (int gg = 0; gg < 4; gg++) {
            const int n = gg * 64 + w8 * 8 + g;
            #pragma unroll
            for (int kt = 0; kt < 4; kt++) {
                const int k0 = kt * 16 + t4 * 2;
                bw2[gg][kt][0] = packh(W2[(size_t)k0 * NG + n],       W2[(size_t)(k0 + 1) * NG + n]);
                bw2[gg][kt][1] = packh(W2[(size_t)(k0 + 8) * NG + n], W2[(size_t)(k0 + 9) * NG + n]);
                bu2[gg][kt][0] = packh(U2[(size_t)k0 * NG + n],       U2[(size_t)(k0 + 1) * NG + n]);
                bu2[gg][kt][1] = packh(U2[(size_t)(k0 + 8) * NG + n], U2[(size_t)(k0 + 9) * NG + n]);
            }
            const int col = gg * 64 + w8 * 8 + t4 * 2;
            rb2[gg] = packh(b2[col], b2[col + 1]);
        }
        BAR512();                                   // bar0
        BAR512();                                   // bar1 (warm-up; h1(0) ready after)

        uint32_t c2s[2][2] = {{0u, 0u}, {0u, 0u}};

        for (int t = 1; t < SEQLEN; ++t) {
            const uint32_t h1rd = (t & 1) ? h1b1 : h1b0;
            const uint32_t h2rd = (t & 1) ? h2b1 : h2b0;
            uint32_t acc2[2][4][2];
            #pragma unroll
            for (int mt = 0; mt < 2; mt++)
                #pragma unroll
                for (int gg = 0; gg < 4; gg++) { acc2[mt][gg][0] = rb2[gg]; acc2[mt][gg][1] = rb2[gg]; }
            #pragma unroll
            for (int kt = 0; kt < 4; kt++) {
                uint32_t a0[4], a1[4];
                ldmx4(a0, h1rd + a_lane_h + (uint32_t)(kt * 32));
                ldmx4(a1, h1rd + a_lane_h + (uint32_t)(16 * 144 + kt * 32));
                #pragma unroll
                for (int gg = 0; gg < 4; gg++) {
                    mma16816hh(acc2[0][gg], a0, bw2[gg][kt]);
                    mma16816hh(acc2[1][gg], a1, bw2[gg][kt]);
                }
            }
            #pragma unroll
            for (int kt = 0; kt < 4; kt++) {
                uint32_t a0[4], a1[4];
                ldmx4(a0, h2rd + a_lane_h + (uint32_t)(kt * 32));
                ldmx4(a1, h2rd + a_lane_h + (uint32_t)(16 * 144 + kt * 32));
                #pragma unroll
                for (int gg = 0; gg < 4; gg++) {
                    mma16816hh(acc2[0][gg], a0, bu2[gg][kt]);
                    mma16816hh(acc2[1][gg], a1, bu2[gg][kt]);
                }
            }
            char* h2wr = sm + H2_OFF + ((t & 1) ^ 1) * 4608;
            #pragma unroll
            for (int mt = 0; mt < 2; mt++)
                #pragma unroll
                for (int rs = 0; rs < 2; rs++) {
                    const int row = mt * 16 + g + rs * 8;
                    uint32_t hv = lstm_cell2h(acc2[mt][0][rs], acc2[mt][1][rs],
                                              acc2[mt][2][rs], acc2[mt][3][rs], c2s[mt][rs]);
                    *(uint32_t*)(h2wr + row * 144 + colb) = hv;
                }
            BAR512();                               // bar2..80
        }

        // ---- t = 80 epilogue: h2(79) from h1(79), h2(78) (both buf0) ----
        {
            uint32_t acc2[2][4][2];
            #pragma unroll
            for (int mt = 0; mt < 2; mt++)
                #pragma unroll
                for (int gg = 0; gg < 4; gg++) { acc2[mt][gg][0] = rb2[gg]; acc2[mt][gg][1] = rb2[gg]; }
            #pragma unroll
            for (int kt = 0; kt < 4; kt++) {
                uint32_t a0[4], a1[4];
                ldmx4(a0, h1b0 + a_lane_h + (uint32_t)(kt * 32));
                ldmx4(a1, h1b0 + a_lane_h + (uint32_t)(16 * 144 + kt * 32));
                #pragma unroll
                for (int gg = 0; gg < 4; gg++) {
                    mma16816hh(acc2[0][gg], a0, bw2[gg][kt]);
                    mma16816hh(acc2[1][gg], a1, bw2[gg][kt]);
                }
            }
            #pragma unroll
            for (int kt = 0; kt < 4; kt++) {
                uint32_t a0[4], a1[4];
                ldmx4(a0, h2b0 + a_lane_h + (uint32_t)(kt * 32));
                ldmx4(a1, h2b0 + a_lane_h + (uint32_t)(16 * 144 + kt * 32));
                #pragma unroll
                for (int gg = 0; gg < 4; gg++) {
                    mma16816hh(acc2[0][gg], a0, bu2[gg][kt]);
                    mma16816hh(acc2[1][gg], a1, bu2[gg][kt]);
                }
            }
            float (*hfin)[68] = reinterpret_cast<float(*)[68]>(sm + XS_OFF);
            #pragma unroll
            for (int mt = 0; mt < 2; mt++)
                #pragma unroll
                for (int rs = 0; rs < 2; rs++) {
                    const int row = mt * 16 + g + rs * 8;
                    uint32_t hv = lstm_cell2h(acc2[mt][0][rs], acc2[mt][1][rs],
                                              acc2[mt][2][rs], acc2[mt][3][rs], c2s[mt][rs]);
                    float2 f = h2tof2(hv);
                    hfin[row][w8 * 8 + t4 * 2]     = f.x;
                    hfin[row][w8 * 8 + t4 * 2 + 1] = f.y;
                }
        }
        BAR512();                                   // bar81 (final)
    }

    // -------------------- dense head --------------------
    if (tid < 32) {
        float (*hfin)[68] = reinterpret_cast<float(*)[68]>(sm + XS_OFF);
        float s = bd[0];
        #pragma unroll
        for (int u = 0; u < 64; u++) s += hfin[tid][u] * Wd[u];
        out[b0 + tid] = fmaf(0.5f, tanhapx(0.5f * s), 0.5f);
    }
}

// ---------------------------------------------------------------------------
extern "C" void kernel_launch(void* const* d_in, const int* in_sizes, int n_in,
                              void* d_out, int out_size)
{
    const int*   tokens = (const int*)  d_in[0];
    const float* emb    = (const float*)d_in[1];
    const float* W1     = (const float*)d_in[2];
    const float* U1     = (const float*)d_in[3];
    const float* b1     = (const float*)d_in[4];
    const float* W2     = (const float*)d_in[5];
    const float* U2     = (const float*)d_in[6];
    const float* b2     = (const float*)d_in[7];
    const float* Wd     = (const float*)d_in[8];
    const float* bd     = (const float*)d_in[9];
    float* out = (float*)d_out;

    const int smem_gp = 2 * 128 * (112 + 8) * 2;   // 61440
    cudaFuncSetAttribute(gemm_P,  cudaFuncAttributeMaxDynamicSharedMemorySize, smem_gp);
    cudaFuncSetAttribute(lstm_ws, cudaFuncAttributeMaxDynamicSharedMemorySize, SM_TOTAL);

    conv_w1_kernel<<<256 * 128 / 256, 256>>>(W1);
    dim3 pgrid(2, 79);
    gemm_P<<<pgrid, 256, smem_gp>>>(emb, b1);

    lstm_ws<<<BATCHN / 32, 512, SM_TOTAL>>>(tokens, U1, W2, U2, b2, Wd, bd, out);
}

// round 17
// speedup vs baseline: 1.1579x; 1.0184x over previous
#include <cuda_runtime.h>
#include <cuda_bf16.h>
#include <cuda_fp16.h>
#include <cstdint>

#define BATCHN 4096
#define SEQLEN 80
#define EMBD   100
#define UNITS  64
#define NG     256                 // 4*UNITS gates
#define PROWS  (79 * 128)          // vocab padded to m-tiles

// ---------------- device scratch (allocation-free: device globals) ----------
__device__ uint16_t g_P[(size_t)PROWS * 256];            // f16 table: emb@W1 + b1

// ---------------- helpers ---------------------------------------------------
__device__ __forceinline__ float tanhapx(float x) {
    float y; asm("tanh.approx.f32 %0, %1;" : "=f"(y) : "f"(x)); return y;
}
__device__ __forceinline__ uint32_t smem_u32(const void* p) {
    uint32_t a;
    asm("{ .reg .u64 t; cvta.to.shared.u64 t, %1; cvt.u32.u64 %0, t; }" : "=r"(a) : "l"(p));
    return a;
}
__device__ __forceinline__ uint32_t hmul2(uint32_t a, uint32_t b) {
    uint32_t d; asm("mul.rn.f16x2 %0,%1,%2;" : "=r"(d) : "r"(a), "r"(b)); return d;
}
__device__ __forceinline__ uint32_t hfma2(uint32_t a, uint32_t b, uint32_t c) {
    uint32_t d; asm("fma.rn.f16x2 %0,%1,%2,%3;" : "=r"(d) : "r"(a), "r"(b), "r"(c)); return d;
}
__device__ __forceinline__ uint32_t htanh2(uint32_t a) {
    uint32_t d; asm("tanh.approx.f16x2 %0,%1;" : "=r"(d) : "r"(a)); return d;
}
__device__ __forceinline__ uint32_t packh(float lo, float hi) {
    uint32_t d; asm("cvt.rn.f16x2.f32 %0,%1,%2;" : "=r"(d) : "f"(hi), "f"(lo)); return d;
}
__device__ __forceinline__ float2 h2tof2(uint32_t h) {
    float lo, hi;
    asm("{ .reg .b16 l,h; mov.b32 {l,h}, %2; cvt.f32.f16 %0, l; cvt.f32.f16 %1, h; }"
        : "=f"(lo), "=f"(hi) : "r"(h));
    return make_float2(lo, hi);
}
// bf16 HMMA, f32 acc (P-table GEMM only)
__device__ __forceinline__ void mma16816(float* d, const uint32_t* a, const uint32_t* b) {
    asm volatile(
        "mma.sync.aligned.m16n8k16.row.col.f32.bf16.bf16.f32 "
        "{%0,%1,%2,%3}, {%4,%5,%6,%7}, {%8,%9}, {%0,%1,%2,%3};"
        : "+f"(d[0]), "+f"(d[1]), "+f"(d[2]), "+f"(d[3])
        : "r"(a[0]), "r"(a[1]), "r"(a[2]), "r"(a[3]), "r"(b[0]), "r"(b[1]));
}
// f16 HMMA, f16 acc (scan)
__device__ __forceinline__ void mma16816hh(uint32_t* d, const uint32_t* a, const uint32_t* b) {
    asm volatile(
        "mma.sync.aligned.m16n8k16.row.col.f16.f16.f16.f16 "
        "{%0,%1}, {%2,%3,%4,%5}, {%6,%7}, {%0,%1};"
        : "+r"(d[0]), "+r"(d[1])
        : "r"(a[0]), "r"(a[1]), "r"(a[2]), "r"(a[3]), "r"(b[0]), "r"(b[1]));
}
__device__ __forceinline__ void ldmx4(uint32_t* r, uint32_t addr) {
    asm volatile("ldmatrix.sync.aligned.m8n8.x4.shared.b16 {%0,%1,%2,%3}, [%4];"
        : "=r"(r[0]), "=r"(r[1]), "=r"(r[2]), "=r"(r[3]) : "r"(addr));
}
__device__ __forceinline__ void cpa16(uint32_t dst, const void* gsrc) {
    asm volatile("{ .reg .u64 ga; cvta.to.global.u64 ga, %1; "
                 "cp.async.cg.shared.global [%0], [ga], 16; }"
                 :: "r"(dst), "l"(gsrc) : "memory");
}
#define CPA_COMMIT() asm volatile("cp.async.commit_group;" ::: "memory")
#define CPA_WAIT0()  asm volatile("cp.async.wait_group 0;" ::: "memory")
#define BAR512()     asm volatile("bar.sync 0, 512;" ::: "memory")

// f16x2 LSTM cell pair (R11 numerics: sigmoid via 0.5*tanh(0.5x)+0.5)
__device__ __forceinline__ uint32_t lstm_cell2h(
    uint32_t zi, uint32_t zf, uint32_t zg, uint32_t zo, uint32_t& c2)
{
    const uint32_t H05 = 0x38003800u;   // (0.5, 0.5)
    uint32_t si = hfma2(htanh2(hmul2(zi, H05)), H05, H05);
    uint32_t sf = hfma2(htanh2(hmul2(zf, H05)), H05, H05);
    uint32_t tg = htanh2(zg);
    uint32_t so = hfma2(htanh2(hmul2(zo, H05)), H05, H05);
    c2 = hfma2(sf, c2, hmul2(si, tg));
    return hmul2(so, htanh2(c2));
}

// ---------------------------------------------------------------------------
// P-table GEMM: P[v][0:256] = emb[v]@W1 + b1 (f16 out). Grid (2, 79).
// BOTH conversions fused in: A = emb f32->bf16 gather; B = W1 f32 transpose
// (coalesced row-fast loads from the L2-resident 100KB W1) -> bf16.
// ---------------------------------------------------------------------------
__global__ void __launch_bounds__(256, 2) gemm_P(
    const float* __restrict__ emb, const float* __restrict__ W1,
    const float* __restrict__ bias)
{
    constexpr int K = 112, SA = K + 8, KH = K / 2;
    extern __shared__ __nv_bfloat16 smbf[];
    __nv_bfloat16* Asm = smbf;
    __nv_bfloat16* Bsm = smbf + 128 * SA;

    const int tid = threadIdx.x;
    const int m0  = blockIdx.y * 128;
    const int c0  = blockIdx.x * 128;

    // stage A: gather emb rows, convert f32->bf16, zero-pad K 100->112
    for (int idx = tid; idx < 128 * KH; idx += 256) {
        int row = idx / KH, kc = (idx - row * KH) * 2;
        int m = m0 + row; if (m > 9999) m = 9999;
        float f0 = 0.f, f1 = 0.f;
        if (kc < EMBD) {                 // kc even, EMBD=100 -> kc+1 < EMBD too
            const float* e = emb + (size_t)m * EMBD + kc;
            f0 = e[0]; f1 = e[1];
        }
        __nv_bfloat162 v = __float22bfloat162_rn(make_float2(f0, f1));
        *(uint32_t*)&Asm[row * SA + kc] = *(uint32_t*)&v;
    }
    // stage B: W1^T tile, row-fast loop -> coalesced f32 loads, f32->bf16
    for (int idx = tid; idx < KH * 128; idx += 256) {
        int kci = idx >> 7, row = idx & 127;       // kc pair index, n-row
        int kc = kci * 2;
        float f0 = 0.f, f1 = 0.f;
        if (kc < EMBD) {
            f0 = W1[(size_t)kc * NG + c0 + row];
            f1 = W1[(size_t)(kc + 1) * NG + c0 + row];
        }
        __nv_bfloat162 v = __float22bfloat162_rn(make_float2(f0, f1));
        *(uint32_t*)&Bsm[row * SA + kc] = *(uint32_t*)&v;
    }
    __syncthreads();

    const int wid  = tid >> 5, lid = tid & 31;
    const int wrow = wid & 3, wcol = wid >> 2;
    const int g    = lid >> 2, t = lid & 3;

    const uint32_t a_base = smem_u32(Asm);
    const uint32_t b_base = smem_u32(Bsm);
    const uint32_t a_lane = (uint32_t)((wrow * 32 + (lid & 15)) * SA * 2 + (lid >> 4) * 16);
    const uint32_t b_lane = (uint32_t)((wcol * 64 + (lid >> 4) * 8 + (lid & 7)) * SA * 2 +
                                       ((lid >> 3) & 1) * 16);

    float acc[2][8][4];
    #pragma unroll
    for (int mt = 0; mt < 2; mt++)
        #pragma unroll
        for (int nt = 0; nt < 8; nt++)
            #pragma unroll
            for (int r = 0; r < 4; r++) acc[mt][nt][r] = 0.f;

    #pragma unroll
    for (int s = 0; s < K / 16; s++) {
        uint32_t af[2][4], bfr[8][2];
        #pragma unroll
        for (int mt = 0; mt < 2; mt++)
            ldmx4(af[mt], a_base + a_lane + (uint32_t)(mt * 16 * SA * 2 + s * 32));
        #pragma unroll
        for (int np = 0; np < 4; np++) {
            uint32_t bq[4];
            ldmx4(bq, b_base + b_lane + (uint32_t)(np * 16 * SA * 2 + s * 32));
            bfr[np * 2][0] = bq[0]; bfr[np * 2][1] = bq[1];
            bfr[np * 2 + 1][0] = bq[2]; bfr[np * 2 + 1][1] = bq[3];
        }
        #pragma unroll
        for (int mt = 0; mt < 2; mt++)
            #pragma unroll
            for (int nt = 0; nt < 8; nt++)
                mma16816(acc[mt][nt], af[mt], bfr[nt]);
    }

    #pragma unroll
    for (int nt = 0; nt < 8; nt++) {
        const int col = c0 + wcol * 64 + nt * 8 + t * 2;
        float2 bb = *(const float2*)&bias[col];
        #pragma unroll
        for (int mt = 0; mt < 2; mt++) {
            const int row = m0 + wrow * 32 + mt * 16 + g;
            *(uint32_t*)&g_P[(size_t)row * 256 + col] =
                packh(acc[mt][nt][0] + bb.x, acc[mt][nt][1] + bb.y);
            *(uint32_t*)&g_P[(size_t)(row + 8) * 256 + col] =
                packh(acc[mt][nt][2] + bb.x, acc[mt][nt][3] + bb.y);
        }
    }
}

// ---------------------------------------------------------------------------
// Warp-specialized fused scan (R11 best core): 128 CTAs x 512 thr, 32 rows.
// Warps 0-7  (L1): z1 = P[token] + h1@U1
// Warps 8-15 (L2): z2 = b2 + h1@W2 + h2@U2, lag 1
// One bar.sync 0,512 per step.
// ---------------------------------------------------------------------------
#define XS_OFF  0                      // 2 x 32 x 528  = 33792 (f16 P rows)
#define H1_OFF  33792                  // 2 x 32 x 144  = 9216
#define H2_OFF  43008                  // 9216
#define TOK_OFF 52224                  // 32 x 80 x 2   = 5120
#define SM_TOTAL 57344

__global__ void __launch_bounds__(512, 1) lstm_ws(
    const int*   __restrict__ tokens,
    const float* __restrict__ U1,
    const float* __restrict__ W2,
    const float* __restrict__ U2,
    const float* __restrict__ b2,
    const float* __restrict__ Wd,
    const float* __restrict__ bd,
    float*       __restrict__ out)
{
    extern __shared__ char sm[];
    const int tid = threadIdx.x, wid = tid >> 5, lid = tid & 31;
    const int g = lid >> 2, t4 = lid & 3;
    const int w8 = wid & 7;
    const int b0 = blockIdx.x * 32;

    uint16_t* toks = (uint16_t*)(sm + TOK_OFF);

    {   // zero h buffers (exactly h1+h2: 18432 bytes)
        uint32_t* z1 = (uint32_t*)(sm + H1_OFF);
        for (int i = tid; i < 18432 / 4; i += 512) z1[i] = 0u;
    }
    for (int idx = tid; idx < 32 * SEQLEN; idx += 512)
        toks[idx] = (uint16_t)tokens[(size_t)(b0 + idx / SEQLEN) * SEQLEN + idx % SEQLEN];
    __syncthreads();

    const uint32_t xs_b = smem_u32(sm + XS_OFF);
    const uint32_t h1b0 = smem_u32(sm + H1_OFF), h1b1 = h1b0 + 4608;
    const uint32_t h2b0 = smem_u32(sm + H2_OFF), h2b1 = h2b0 + 4608;
    const uint32_t a_lane_h = (uint32_t)((lid & 15) * 144 + (lid >> 4) * 16);
    const int colb = (w8 * 8 + t4 * 2) * 2;

    if (wid < 8) {
        // =================== layer-1 group ===================
        auto stage_x = [&](int buf, int t) {
            const uint32_t dbase = xs_b + buf * 16896;
            #pragma unroll
            for (int i = 0; i < 4; i++) {
                int idx = tid + i * 256;       // 32 rows x 32 chunks of 16B
                int row = idx >> 5, ch = idx & 31;
                cpa16(dbase + row * 528 + ch * 16,
                      g_P + (size_t)toks[row * SEQLEN + t] * 256 + ch * 8);
            }
        };
        stage_x(0, 0);
        CPA_COMMIT();

        uint32_t bu1[4][4][2];
        #pragma unroll
        for (int gg = 0; gg < 4; gg++) {
            const int n = gg * 64 + w8 * 8 + g;
            #pragma unroll
            for (int kt = 0; kt < 4; kt++) {
                const int k0 = kt * 16 + t4 * 2;
                bu1[gg][kt][0] = packh(U1[(size_t)k0 * NG + n],       U1[(size_t)(k0 + 1) * NG + n]);
                bu1[gg][kt][1] = packh(U1[(size_t)(k0 + 8) * NG + n], U1[(size_t)(k0 + 9) * NG + n]);
            }
        }
        CPA_WAIT0();
        BAR512();                                   // bar0: x(0)+weights ready

        uint32_t c1[2][2] = {{0u, 0u}, {0u, 0u}};

        // ---- t = 0 peel: h1(0) = cell(x(0)); stage x(1) ----
        stage_x(1, 1);
        CPA_COMMIT();
        {
            const char* xb = sm + XS_OFF;
            char* h1wr = sm + H1_OFF + 4608;        // buf1
            #pragma unroll
            for (int mt = 0; mt < 2; mt++)
                #pragma unroll
                for (int rs = 0; rs < 2; rs++) {
                    const int row = mt * 16 + g + rs * 8;
                    uint32_t z0 = *(const uint32_t*)(xb + row * 528 + 0 * 128 + colb);
                    uint32_t z1v = *(const uint32_t*)(xb + row * 528 + 1 * 128 + colb);
                    uint32_t z2 = *(const uint32_t*)(xb + row * 528 + 2 * 128 + colb);
                    uint32_t z3 = *(const uint32_t*)(xb + row * 528 + 3 * 128 + colb);
                    uint32_t hv = lstm_cell2h(z0, z1v, z2, z3, c1[mt][rs]);
                    *(uint32_t*)(h1wr + row * 144 + colb) = hv;
                }
        }
        CPA_WAIT0();
        BAR512();                                   // bar1

        for (int t = 1; t < SEQLEN; ++t) {
            if (t + 1 < SEQLEN) stage_x((t + 1) & 1, t + 1);
            CPA_COMMIT();

            const uint32_t h1rd = (t & 1) ? h1b1 : h1b0;
            uint32_t acc1[2][4][2];
            const char* xb = sm + XS_OFF + (t & 1) * 16896;
            #pragma unroll
            for (int mt = 0; mt < 2; mt++)
                #pragma unroll
                for (int gg = 0; gg < 4; gg++) {
                    acc1[mt][gg][0] = *(const uint32_t*)(xb + (mt * 16 + g) * 528 + gg * 128 + colb);
                    acc1[mt][gg][1] = *(const uint32_t*)(xb + (mt * 16 + g + 8) * 528 + gg * 128 + colb);
                }
            #pragma unroll
            for (int kt = 0; kt < 4; kt++) {
                uint32_t a0[4], a1[4];
                ldmx4(a0, h1rd + a_lane_h + (uint32_t)(kt * 32));
                ldmx4(a1, h1rd + a_lane_h + (uint32_t)(16 * 144 + kt * 32));
                #pragma unroll
                for (int gg = 0; gg < 4; gg++) {
                    mma16816hh(acc1[0][gg], a0, bu1[gg][kt]);
                    mma16816hh(acc1[1][gg], a1, bu1[gg][kt]);
                }
            }
            char* h1wr = sm + H1_OFF + ((t & 1) ^ 1) * 4608;
            #pragma unroll
            for (int mt = 0; mt < 2; mt++)
                #pragma unroll
                for (int rs = 0; rs < 2; rs++) {
                    const int row = mt * 16 + g + rs * 8;
                    uint32_t hv = lstm_cell2h(acc1[mt][0][rs], acc1[mt][1][rs],
                                              acc1[mt][2][rs], acc1[mt][3][rs], c1[mt][rs]);
                    *(uint32_t*)(h1wr + row * 144 + colb) = hv;
                }
            CPA_WAIT0();
            BAR512();                               // bar2..80
        }
        BAR512();                                   // bar81 (final)
    } else {
        // =================== layer-2 group ===================
        uint32_t bw2[4][4][2], bu2[4][4][2], rb2[4];
        #pragma unroll
        for (int gg = 0; gg < 4; gg++) {
            const int n = gg * 64 + w8 * 8 + g;
            #pragma unroll
            for (int kt = 0; kt < 4; kt++) {
                const int k0 = kt * 16 + t4 * 2;
                bw2[gg][kt][0] = packh(W2[(size_t)k0 * NG + n],       W2[(size_t)(k0 + 1) * NG + n]);
                bw2[gg][kt][1] = packh(W2[(size_t)(k0 + 8) * NG + n], W2[(size_t)(k0 + 9) * NG + n]);
                bu2[gg][kt][0] = packh(U2[(size_t)k0 * NG + n],       U2[(size_t)(k0 + 1) * NG + n]);
                bu2[gg][kt][1] = packh(U2[(size_t)(k0 + 8) * NG + n], U2[(size_t)(k0 + 9) * NG + n]);
            }
            const int col = gg * 64 + w8 * 8 + t4 * 2;
            rb2[gg] = packh(b2[col], b2[col + 1]);
        }
        BAR512();                                   // bar0
        BAR512();                                   // bar1 (warm-up; h1(0) ready after)

        uint32_t c2s[2][2] = {{0u, 0u}, {0u, 0u}};

        for (int t = 1; t < SEQLEN; ++t) {
            const uint32_t h1rd = (t & 1) ? h1b1 : h1b0;
            const uint32_t h2rd = (t & 1) ? h2b1 : h2b0;
            uint32_t acc2[2][4][2];
            #pragma unroll
            for (int mt = 0; mt < 2; mt++)
                #pragma unroll
                for (int gg = 0; gg < 4; gg++) { acc2[mt][gg][0] = rb2[gg]; acc2[mt][gg][1] = rb2[gg]; }
            #pragma unroll
            for (int kt = 0; kt < 4; kt++) {
                uint32_t a0[4], a1[4];
                ldmx4(a0, h1rd + a_lane_h + (uint32_t)(kt * 32));
                ldmx4(a1, h1rd + a_lane_h + (uint32_t)(16 * 144 + kt * 32));
                #pragma unroll
                for (int gg = 0; gg < 4; gg++) {
                    mma16816hh(acc2[0][gg], a0, bw2[gg][kt]);
                    mma16816hh(acc2[1][gg], a1, bw2[gg][kt]);
                }
            }
            #pragma unroll
            for (int kt = 0; kt < 4; kt++) {
                uint32_t a0[4], a1[4];
                ldmx4(a0, h2rd + a_lane_h + (uint32_t)(kt * 32));
                ldmx4(a1, h2rd + a_lane_h + (uint32_t)(16 * 144 + kt * 32));
                #pragma unroll
                for (int gg = 0; gg < 4; gg++) {
                    mma16816hh(acc2[0][gg], a0, bu2[gg][kt]);
                    mma16816hh(acc2[1][gg], a1, bu2[gg][kt]);
                }
            }
            char* h2wr = sm + H2_OFF + ((t & 1) ^ 1) * 4608;
            #pragma unroll
            for (int mt = 0; mt < 2; mt++)
                #pragma unroll
                for (int rs = 0; rs < 2; rs++) {
                    const int row = mt * 16 + g + rs * 8;
                    uint32_t hv = lstm_cell2h(acc2[mt][0][rs], acc2[mt][1][rs],
                                              acc2[mt][2][rs], acc2[mt][3][rs], c2s[mt][rs]);
                    *(uint32_t*)(h2wr + row * 144 + colb) = hv;
                }
            BAR512();                               // bar2..80
        }

        // ---- t = 80 epilogue: h2(79) from h1(79), h2(78) (both buf0) ----
        {
            uint32_t acc2[2][4][2];
            #pragma unroll
            for (int mt = 0; mt < 2; mt++)
                #pragma unroll
                for (int gg = 0; gg < 4; gg++) { acc2[mt][gg][0] = rb2[gg]; acc2[mt][gg][1] = rb2[gg]; }
            #pragma unroll
            for (int kt = 0; kt < 4; kt++) {
                uint32_t a0[4], a1[4];
                ldmx4(a0, h1b0 + a_lane_h + (uint32_t)(kt * 32));
                ldmx4(a1, h1b0 + a_lane_h + (uint32_t)(16 * 144 + kt * 32));
                #pragma unroll
                for (int gg = 0; gg < 4; gg++) {
                    mma16816hh(acc2[0][gg], a0, bw2[gg][kt]);
                    mma16816hh(acc2[1][gg], a1, bw2[gg][kt]);
                }
            }
            #pragma unroll
            for (int kt = 0; kt < 4; kt++) {
                uint32_t a0[4], a1[4];
                ldmx4(a0, h2b0 + a_lane_h + (uint32_t)(kt * 32));
                ldmx4(a1, h2b0 + a_lane_h + (uint32_t)(16 * 144 + kt * 32));
                #pragma unroll
                for (int gg = 0; gg < 4; gg++) {
                    mma16816hh(acc2[0][gg], a0, bu2[gg][kt]);
                    mma16816hh(acc2[1][gg], a1, bu2[gg][kt]);
                }
            }
            float (*hfin)[68] = reinterpret_cast<float(*)[68]>(sm + XS_OFF);
            #pragma unroll
            for (int mt = 0; mt < 2; mt++)
                #pragma unroll
                for (int rs = 0; rs < 2; rs++) {
                    const int row = mt * 16 + g + rs * 8;
                    uint32_t hv = lstm_cell2h(acc2[mt][0][rs], acc2[mt][1][rs],
                                              acc2[mt][2][rs], acc2[mt][3][rs], c2s[mt][rs]);
                    float2 f = h2tof2(hv);
                    hfin[row][w8 * 8 + t4 * 2]     = f.x;
                    hfin[row][w8 * 8 + t4 * 2 + 1] = f.y;
                }
        }
        BAR512();                                   // bar81 (final)
    }

    // -------------------- dense head --------------------
    if (tid < 32) {
        float (*hfin)[68] = reinterpret_cast<float(*)[68]>(sm + XS_OFF);
        float s = bd[0];
        #pragma unroll
        for (int u = 0; u < 64; u++) s += hfin[tid][u] * Wd[u];
        out[b0 + tid] = fmaf(0.5f, tanhapx(0.5f * s), 0.5f);
    }
}

// ---------------------------------------------------------------------------
extern "C" void kernel_launch(void* const* d_in, const int* in_sizes, int n_in,
                              void* d_out, int out_size)
{
    const int*   tokens = (const int*)  d_in[0];
    const float* emb    = (const float*)d_in[1];
    const float* W1     = (const float*)d_in[2];
    const float* U1     = (const float*)d_in[3];
    const float* b1     = (const float*)d_in[4];
    const float* W2     = (const float*)d_in[5];
    const float* U2     = (const float*)d_in[6];
    const float* b2     = (const float*)d_in[7];
    const float* Wd     = (const float*)d_in[8];
    const float* bd     = (const float*)d_in[9];
    float* out = (float*)d_out;

    const int smem_gp = 2 * 128 * (112 + 8) * 2;   // 61440
    cudaFuncSetAttribute(gemm_P,  cudaFuncAttributeMaxDynamicSharedMemorySize, smem_gp);
    cudaFuncSetAttribute(lstm_ws, cudaFuncAttributeMaxDynamicSharedMemorySize, SM_TOTAL);

    dim3 pgrid(2, 79);
    gemm_P<<<pgrid, 256, smem_gp>>>(emb, W1, b1);

    lstm_ws<<<BATCHN / 32, 512, SM_TOTAL>>>(tokens, U1, W2, U2, b2, Wd, bd, out);
}